// round 1
// baseline (speedup 1.0000x reference)
#include <cuda_runtime.h>
#include <math.h>

#define B_   16
#define C_   256
#define H_   32
#define W_   32
#define HW   1024
#define HM   128
#define WM   128
#define HWM  16384
#define N_   100
#define F_   1024
#define NH_  8
#define HD   32
#define L_   2
#define EPSF 1e-5f

// ---- output layout (flattened tuple: queries, pred_masks, intermediate) ----
#define OUT_Q     0
#define OUT_PRED  (B_*N_*C_)                      // 409600
#define OUT_INTER (OUT_PRED + B_*N_*HWM)          // 409600 + 26214400

// ---- scratch offsets (floats) ----
#define OFF_Q    0L
#define OFF_E1   409600L
#define OFF_E    819200L
#define OFF_QB   1228800L
#define OFF_OB   1638400L
#define OFF_TMP  2048000L
#define OFF_FFH  2457600L                          // 1,638,400 floats
#define OFF_FE   4096000L                          // 4,194,304 floats
#define OFF_KB   8290304L
#define OFF_VB   12484608L
#define SCRATCH_FLOATS (12484608L + 4194304L)      // 16,678,912 floats (~64 MB)

__device__ float g_scratch[SCRATCH_FLOATS];
__device__ unsigned char g_am[B_ * N_ * HW];

// ============================================================
// Generic tiled SGEMM: C[m,n] = A[m,k] * B[k,n] (+bias) (relu)
// 64x64 tile, BK=16, 256 threads, 4x4 per thread, batched via z.
// K must be multiple of 16, N multiple of 64; M guarded.
// ============================================================
__global__ void gemm64(const float* __restrict__ A, const float* __restrict__ B,
                       const float* __restrict__ bias, float* __restrict__ C,
                       int M, int N, int K, int relu,
                       long sA, long sB, long sC)
{
    const int BM = 64, BN = 64, BK = 16;
    __shared__ float As[BK][BM + 4];
    __shared__ float Bs[BK][BN];

    long bz = blockIdx.z;
    A += bz * sA;  B += bz * sB;  C += bz * sC;

    int tid = threadIdx.x;
    int brow = blockIdx.y * BM;
    int bcol = blockIdx.x * BN;
    int tx = tid & 15, ty = tid >> 4;

    int arow = tid >> 2;            // 0..63
    int ak   = (tid & 3) * 4;       // 0,4,8,12
    int bro  = tid >> 4;            // 0..15
    int bco  = (tid & 15) * 4;      // 0..60

    float acc[4][4];
#pragma unroll
    for (int i = 0; i < 4; i++)
#pragma unroll
        for (int j = 0; j < 4; j++) acc[i][j] = 0.f;

    for (int k0 = 0; k0 < K; k0 += BK) {
        float4 av;
        if (brow + arow < M)
            av = *(const float4*)(A + (long)(brow + arow) * K + k0 + ak);
        else
            av = make_float4(0.f, 0.f, 0.f, 0.f);
        As[ak + 0][arow] = av.x;
        As[ak + 1][arow] = av.y;
        As[ak + 2][arow] = av.z;
        As[ak + 3][arow] = av.w;

        float4 bv = *(const float4*)(B + (long)(k0 + bro) * N + bcol + bco);
        *(float4*)&Bs[bro][bco] = bv;
        __syncthreads();

#pragma unroll
        for (int kk = 0; kk < BK; kk++) {
            float ra[4], rb[4];
#pragma unroll
            for (int i = 0; i < 4; i++) ra[i] = As[kk][ty * 4 + i];
#pragma unroll
            for (int j = 0; j < 4; j++) rb[j] = Bs[kk][tx * 4 + j];
#pragma unroll
            for (int i = 0; i < 4; i++)
#pragma unroll
                for (int j = 0; j < 4; j++)
                    acc[i][j] += ra[i] * rb[j];
        }
        __syncthreads();
    }

#pragma unroll
    for (int i = 0; i < 4; i++) {
        int r = brow + ty * 4 + i;
        if (r >= M) continue;
#pragma unroll
        for (int j = 0; j < 4; j++) {
            int c = bcol + tx * 4 + j;
            float v = acc[i][j];
            if (bias) v += bias[c];
            if (relu) v = fmaxf(v, 0.f);
            C[(long)r * N + c] = v;
        }
    }
}

// ============================================================
// feats transpose: (B, C, HW) -> (B, HW, C)
// ============================================================
__global__ void feats_transpose(const float* __restrict__ feat, float* __restrict__ out)
{
    __shared__ float tile[32][33];
    int b  = blockIdx.z;
    int c0 = blockIdx.x * 32;   // over C (8 tiles)
    int s0 = blockIdx.y * 32;   // over HW (32 tiles)
    int tx = threadIdx.x, ty = threadIdx.y; // 32 x 8
#pragma unroll
    for (int i = 0; i < 32; i += 8)
        tile[ty + i][tx] = feat[((long)b * C_ + c0 + ty + i) * HW + s0 + tx];
    __syncthreads();
#pragma unroll
    for (int i = 0; i < 32; i += 8)
        out[((long)b * HW + s0 + ty + i) * C_ + c0 + tx] = tile[tx][ty + i];
}

// ============================================================
// broadcast query_embed -> (B, N, C)
// ============================================================
__global__ void bcast_queries(const float* __restrict__ qe, float* __restrict__ q)
{
    int i = blockIdx.x * blockDim.x + threadIdx.x;
    if (i < B_ * N_ * C_) q[i] = qe[i % (N_ * C_)];
}

// ============================================================
// attention mask: bilinear(sigmoid(cur), 128->32) > 0.5, empty-row fix
// block per (b*N+n), 1024 threads (one per output spatial position)
// ============================================================
__global__ void mask_kernel(const float* __restrict__ cur, unsigned char* __restrict__ am)
{
    int row = blockIdx.x;          // b*N + n
    int t = threadIdx.x;           // 0..1023
    int y = t >> 5, x = t & 31;
    const float* p = cur + (long)row * HWM;
    int r0 = 4 * y + 1, c0 = 4 * x + 1;
    float v00 = p[r0 * WM + c0],       v01 = p[r0 * WM + c0 + 1];
    float v10 = p[(r0 + 1) * WM + c0], v11 = p[(r0 + 1) * WM + c0 + 1];
    float s = 1.f / (1.f + expf(-v00)) + 1.f / (1.f + expf(-v01))
            + 1.f / (1.f + expf(-v10)) + 1.f / (1.f + expf(-v11));
    int m = (0.25f * s) > 0.5f;

    __shared__ int cnt[32];
    unsigned bal = __ballot_sync(0xffffffffu, m);
    if ((t & 31) == 0) cnt[t >> 5] = __popc(bal);
    __syncthreads();
    if (t < 32) {
        int v = cnt[t];
#pragma unroll
        for (int o = 16; o > 0; o >>= 1) v += __shfl_down_sync(0xffffffffu, v, o);
        if (t == 0) cnt[0] = v;
    }
    __syncthreads();
    am[(long)row * HW + t] = (cnt[0] == 0) ? (unsigned char)1 : (unsigned char)m;
}

// ============================================================
// attention: block per (n, h, b), 128 threads
// ============================================================
__global__ void attn_kernel(const float* __restrict__ Q, const float* __restrict__ K,
                            const float* __restrict__ V, const unsigned char* __restrict__ am,
                            float* __restrict__ O)
{
    int n = blockIdx.x, h = blockIdx.y, b = blockIdx.z;
    int t = threadIdx.x;  // 128 threads = 4 warps
    __shared__ float qs[HD];
    __shared__ float sc[HW];
    __shared__ float redm[4];
    __shared__ float reds[4];
    __shared__ float osum[4][HD];

    long qrow = (long)(b * N_ + n);
    if (t < HD) qs[t] = Q[qrow * C_ + h * HD + t];
    __syncthreads();

    const float scale = 0.17677669529663687f;  // 1/sqrt(32)
    const unsigned char* amp = am + qrow * HW;

    float lmax = -1e30f;
#pragma unroll
    for (int i = 0; i < 8; i++) {
        int s = t + i * 128;
        const float4* kp = (const float4*)(K + ((long)(b * HW + s)) * C_ + h * HD);
        float d = 0.f;
#pragma unroll
        for (int j = 0; j < 8; j++) {
            float4 kv = kp[j];
            d += kv.x * qs[j * 4] + kv.y * qs[j * 4 + 1]
               + kv.z * qs[j * 4 + 2] + kv.w * qs[j * 4 + 3];
        }
        d *= scale;
        if (!amp[s]) d = -1e30f;
        sc[s] = d;
        lmax = fmaxf(lmax, d);
    }
    // block max
#pragma unroll
    for (int o = 16; o > 0; o >>= 1) lmax = fmaxf(lmax, __shfl_xor_sync(0xffffffffu, lmax, o));
    if ((t & 31) == 0) redm[t >> 5] = lmax;
    __syncthreads();
    if (t == 0) {
        float m = redm[0];
        for (int i = 1; i < 4; i++) m = fmaxf(m, redm[i]);
        redm[0] = m;
    }
    __syncthreads();
    float mx = redm[0];

    float lsum = 0.f;
#pragma unroll
    for (int i = 0; i < 8; i++) {
        int s = t + i * 128;
        float p = __expf(sc[s] - mx);
        sc[s] = p;
        lsum += p;
    }
#pragma unroll
    for (int o = 16; o > 0; o >>= 1) lsum += __shfl_xor_sync(0xffffffffu, lsum, o);
    if ((t & 31) == 0) reds[t >> 5] = lsum;
    __syncthreads();
    if (t == 0) reds[0] = reds[0] + reds[1] + reds[2] + reds[3];
    __syncthreads();
    float tot = reds[0];

    // o accumulation: thread t handles dim d = t&31, s-chunk (t>>5)
    int d = t & 31, q4 = t >> 5;
    float acc = 0.f;
    for (int s = q4 * 256; s < q4 * 256 + 256; s++)
        acc += sc[s] * V[((long)(b * HW + s)) * C_ + h * HD + d];
    osum[q4][d] = acc;
    __syncthreads();
    if (t < HD) {
        float v = osum[0][t] + osum[1][t] + osum[2][t] + osum[3][t];
        O[qrow * C_ + h * HD + t] = v / tot;
    }
}

// ============================================================
// LayerNorm over C=256, optional residual. block per row, 256 thr.
// ============================================================
__global__ void ln_kernel(const float* __restrict__ X, const float* __restrict__ R,
                          const float* __restrict__ g, const float* __restrict__ be,
                          float* __restrict__ Y)
{
    int row = blockIdx.x;
    int t = threadIdx.x;  // 256
    float x = X[(long)row * C_ + t];
    if (R) x += R[(long)row * C_ + t];

    __shared__ float red[8];
    float s = x;
#pragma unroll
    for (int o = 16; o > 0; o >>= 1) s += __shfl_xor_sync(0xffffffffu, s, o);
    if ((t & 31) == 0) red[t >> 5] = s;
    __syncthreads();
    if (t < 8) {
        float v = red[t];
#pragma unroll
        for (int o = 4; o > 0; o >>= 1) v += __shfl_xor_sync(0xffu, v, o);
        if (t == 0) red[0] = v;
    }
    __syncthreads();
    float mean = red[0] * (1.f / C_);
    float dv = x - mean;
    float s2 = dv * dv;
    __syncthreads();  // everyone has read red[0]
#pragma unroll
    for (int o = 16; o > 0; o >>= 1) s2 += __shfl_xor_sync(0xffffffffu, s2, o);
    if ((t & 31) == 0) red[t >> 5] = s2;
    __syncthreads();
    if (t < 8) {
        float v = red[t];
#pragma unroll
        for (int o = 4; o > 0; o >>= 1) v += __shfl_xor_sync(0xffu, v, o);
        if (t == 0) red[0] = v;
    }
    __syncthreads();
    float var = red[0] * (1.f / C_);
    Y[(long)row * C_ + t] = dv * rsqrtf(var + EPSF) * g[t] + be[t];
}

// ============================================================
// host orchestration
// ============================================================
extern "C" void kernel_launch(void* const* d_in, const int* in_sizes, int n_in,
                              void* d_out, int out_size)
{
    (void)in_sizes; (void)n_in; (void)out_size;
    const float* features      = (const float*)d_in[0];
    const float* mask_features = (const float*)d_in[1];
    const float* query_embed   = (const float*)d_in[2];
    const float* Wq  = (const float*)d_in[3];
    const float* bq  = (const float*)d_in[4];
    const float* Wk  = (const float*)d_in[5];
    const float* bk  = (const float*)d_in[6];
    const float* Wv  = (const float*)d_in[7];
    const float* bv  = (const float*)d_in[8];
    const float* Wo  = (const float*)d_in[9];
    const float* bo  = (const float*)d_in[10];
    const float* g1  = (const float*)d_in[11];
    const float* be1 = (const float*)d_in[12];
    const float* W1  = (const float*)d_in[13];
    const float* b1  = (const float*)d_in[14];
    const float* W2  = (const float*)d_in[15];
    const float* b2  = (const float*)d_in[16];
    const float* g2  = (const float*)d_in[17];
    const float* be2 = (const float*)d_in[18];
    const float* gN  = (const float*)d_in[19];
    const float* beN = (const float*)d_in[20];
    const float* Wm1 = (const float*)d_in[21];
    const float* bm1 = (const float*)d_in[22];
    const float* Wm2 = (const float*)d_in[23];
    const float* bm2 = (const float*)d_in[24];
    float* out = (float*)d_out;

    float* S; cudaGetSymbolAddress((void**)&S, g_scratch);
    unsigned char* AM; cudaGetSymbolAddress((void**)&AM, g_am);

    float* Qcur = S + OFF_Q;
    float* E1   = S + OFF_E1;
    float* E    = S + OFF_E;
    float* QB   = S + OFF_QB;
    float* OB   = S + OFF_OB;
    float* TMP  = S + OFF_TMP;
    float* FFH  = S + OFF_FFH;
    float* FE   = S + OFF_FE;
    float* KB   = S + OFF_KB;
    float* VB   = S + OFF_VB;

    const int MQ = B_ * N_;   // 1600 rows (= 25 * 64)

    feats_transpose<<<dim3(C_ / 32, HW / 32, B_), dim3(32, 8)>>>(features, FE);
    bcast_queries<<<(B_ * N_ * C_ + 255) / 256, 256>>>(query_embed, Qcur);

    for (int l = 0; l < L_; l++) {
        // predict_mask(queries) -> intermediate[l]
        gemm64<<<dim3(C_ / 64, 25, 1), 256>>>(Qcur, Wm1, bm1, E1, MQ, C_, C_, 1, 0, 0, 0);
        gemm64<<<dim3(C_ / 64, 25, 1), 256>>>(E1, Wm2, bm2, E, MQ, C_, C_, 0, 0, 0, 0);
        float* curp = out + OUT_INTER + (long)l * B_ * N_ * HWM;
        gemm64<<<dim3(HWM / 64, 2, B_), 256>>>(E, mask_features, nullptr, curp,
                                               N_, HWM, C_, 0,
                                               (long)N_ * C_, (long)C_ * HWM, (long)N_ * HWM);
        // attention mask from cur
        mask_kernel<<<MQ, 1024>>>(curp, AM);

        // projections
        gemm64<<<dim3(C_ / 64, 25, 1), 256>>>(Qcur, Wq + (long)l * C_ * C_, bq + l * C_,
                                              QB, MQ, C_, C_, 0, 0, 0, 0);
        gemm64<<<dim3(C_ / 64, 256, 1), 256>>>(FE, Wk + (long)l * C_ * C_, bk + l * C_,
                                               KB, B_ * HW, C_, C_, 0, 0, 0, 0);
        gemm64<<<dim3(C_ / 64, 256, 1), 256>>>(FE, Wv + (long)l * C_ * C_, bv + l * C_,
                                               VB, B_ * HW, C_, C_, 0, 0, 0, 0);

        attn_kernel<<<dim3(N_, NH_, B_), 128>>>(QB, KB, VB, AM, OB);

        gemm64<<<dim3(C_ / 64, 25, 1), 256>>>(OB, Wo + (long)l * C_ * C_, bo + l * C_,
                                              TMP, MQ, C_, C_, 0, 0, 0, 0);
        ln_kernel<<<MQ, C_>>>(Qcur, TMP, g1 + l * C_, be1 + l * C_, Qcur);

        // FFN
        gemm64<<<dim3(F_ / 64, 25, 1), 256>>>(Qcur, W1 + (long)l * C_ * F_, b1 + l * F_,
                                              FFH, MQ, F_, C_, 1, 0, 0, 0);
        gemm64<<<dim3(C_ / 64, 25, 1), 256>>>(FFH, W2 + (long)l * F_ * C_, b2 + l * C_,
                                              TMP, MQ, C_, F_, 0, 0, 0, 0);
        ln_kernel<<<MQ, C_>>>(Qcur, TMP, g2 + l * C_, be2 + l * C_, Qcur);
    }

    // final LN -> out queries
    ln_kernel<<<MQ, C_>>>(Qcur, nullptr, gN, beN, out + OUT_Q);

    // final predict_mask on normalized queries -> pred_masks
    gemm64<<<dim3(C_ / 64, 25, 1), 256>>>(out + OUT_Q, Wm1, bm1, E1, MQ, C_, C_, 1, 0, 0, 0);
    gemm64<<<dim3(C_ / 64, 25, 1), 256>>>(E1, Wm2, bm2, E, MQ, C_, C_, 0, 0, 0, 0);
    gemm64<<<dim3(HWM / 64, 2, B_), 256>>>(E, mask_features, nullptr, out + OUT_PRED,
                                           N_, HWM, C_, 0,
                                           (long)N_ * C_, (long)C_ * HWM, (long)N_ * HWM);
}

// round 4
// speedup vs baseline: 1.4226x; 1.4226x over previous
#include <cuda_runtime.h>
#include <math.h>

#define B_   16
#define C_   256
#define H_   32
#define W_   32
#define HW   1024
#define HM   128
#define WM   128
#define HWM  16384
#define N_   100
#define F_   1024
#define NH_  8
#define HD   32
#define L_   2
#define EPSF 1e-5f

#define OUT_Q     0
#define OUT_PRED  (B_*N_*C_)
#define OUT_INTER (OUT_PRED + B_*N_*HWM)

#define OFF_Q    0L
#define OFF_E1   409600L
#define OFF_E    819200L
#define OFF_QB   1228800L
#define OFF_OB   1638400L
#define OFF_TMP  2048000L
#define OFF_FFH  2457600L
#define OFF_FE   4096000L
#define OFF_KB   8290304L
#define OFF_VB   12484608L
#define SCRATCH_FLOATS (12484608L + 4194304L)

__device__ float g_scratch[SCRATCH_FLOATS];
__device__ unsigned char g_am[B_ * N_ * HW];

// ============================================================
// gemm64: 64x64 tile, BK=16, 256 thr, 4x4/thread. For small GEMMs.
// ============================================================
__global__ void gemm64(const float* __restrict__ A, const float* __restrict__ B,
                       const float* __restrict__ bias, float* __restrict__ C,
                       int M, int N, int K, int relu,
                       long sA, long sB, long sC)
{
    const int BM = 64, BN = 64, BK = 16;
    __shared__ float As[BK][BM + 4];
    __shared__ float Bs[BK][BN];

    long bz = blockIdx.z;
    A += bz * sA;  B += bz * sB;  C += bz * sC;

    int tid = threadIdx.x;
    int brow = blockIdx.y * BM;
    int bcol = blockIdx.x * BN;
    int tx = tid & 15, ty = tid >> 4;

    int arow = tid >> 2;
    int ak   = (tid & 3) * 4;
    int bro  = tid >> 4;
    int bco  = (tid & 15) * 4;

    float acc[4][4];
#pragma unroll
    for (int i = 0; i < 4; i++)
#pragma unroll
        for (int j = 0; j < 4; j++) acc[i][j] = 0.f;

    for (int k0 = 0; k0 < K; k0 += BK) {
        float4 av;
        if (brow + arow < M)
            av = *(const float4*)(A + (long)(brow + arow) * K + k0 + ak);
        else
            av = make_float4(0.f, 0.f, 0.f, 0.f);
        As[ak + 0][arow] = av.x;
        As[ak + 1][arow] = av.y;
        As[ak + 2][arow] = av.z;
        As[ak + 3][arow] = av.w;

        float4 bv = *(const float4*)(B + (long)(k0 + bro) * N + bcol + bco);
        *(float4*)&Bs[bro][bco] = bv;
        __syncthreads();

#pragma unroll
        for (int kk = 0; kk < BK; kk++) {
            float ra[4], rb[4];
#pragma unroll
            for (int i = 0; i < 4; i++) ra[i] = As[kk][ty * 4 + i];
#pragma unroll
            for (int j = 0; j < 4; j++) rb[j] = Bs[kk][tx * 4 + j];
#pragma unroll
            for (int i = 0; i < 4; i++)
#pragma unroll
                for (int j = 0; j < 4; j++)
                    acc[i][j] += ra[i] * rb[j];
        }
        __syncthreads();
    }

#pragma unroll
    for (int i = 0; i < 4; i++) {
        int r = brow + ty * 4 + i;
        if (r >= M) continue;
#pragma unroll
        for (int j = 0; j < 4; j++) {
            int c = bcol + tx * 4 + j;
            float v = acc[i][j];
            if (bias) v += bias[c];
            if (relu) v = fmaxf(v, 0.f);
            C[(long)r * N + c] = v;
        }
    }
}

// ============================================================
// gemm128: 128x128 tile, BK=16, 256 thr, 8x8/thread, double-buffered.
// ============================================================
__global__ void __launch_bounds__(256, 2)
gemm128(const float* __restrict__ A, const float* __restrict__ B,
        const float* __restrict__ bias, float* __restrict__ C,
        int M, int N, int K, int relu, long sA, long sB, long sC)
{
    const int BK = 16;
    __shared__ float As[2][BK][128];
    __shared__ float Bs[2][BK][128];

    long bz = blockIdx.z;
    A += bz * sA;  B += bz * sB;  C += bz * sC;

    int tid = threadIdx.x;
    int brow = blockIdx.y * 128;
    int bcol = blockIdx.x * 128;
    int tx = tid & 15, ty = tid >> 4;

    int ar  = tid >> 1;
    int ak  = (tid & 1) * 8;
    int bkr = tid >> 4;
    int bc  = (tid & 15) * 8;

    bool arow_ok = (brow + ar) < M;
    const float* Aptr = A + (long)(brow + ar) * K + ak;
    const float* Bptr = B + (long)bkr * N + bcol + bc;

    float4 a0 = make_float4(0.f,0.f,0.f,0.f), a1 = a0, b0, b1;
    if (arow_ok) { a0 = *(const float4*)(Aptr); a1 = *(const float4*)(Aptr + 4); }
    b0 = *(const float4*)(Bptr); b1 = *(const float4*)(Bptr + 4);

    As[0][ak+0][ar]=a0.x; As[0][ak+1][ar]=a0.y; As[0][ak+2][ar]=a0.z; As[0][ak+3][ar]=a0.w;
    As[0][ak+4][ar]=a1.x; As[0][ak+5][ar]=a1.y; As[0][ak+6][ar]=a1.z; As[0][ak+7][ar]=a1.w;
    *(float4*)&Bs[0][bkr][bc]   = b0;
    *(float4*)&Bs[0][bkr][bc+4] = b1;
    __syncthreads();

    float acc[8][8];
#pragma unroll
    for (int i = 0; i < 8; i++)
#pragma unroll
        for (int j = 0; j < 8; j++) acc[i][j] = 0.f;

    int NT = K / BK;
    int buf = 0;
    for (int t = 0; t < NT; t++) {
        if (t + 1 < NT) {
            const float* Ap = Aptr + (t + 1) * BK;
            if (arow_ok) { a0 = *(const float4*)Ap; a1 = *(const float4*)(Ap + 4); }
            const float* Bp = Bptr + (long)(t + 1) * BK * N;
            b0 = *(const float4*)Bp; b1 = *(const float4*)(Bp + 4);
        }
#pragma unroll
        for (int k = 0; k < BK; k++) {
            float ra[8], rb[8];
            *(float4*)&ra[0] = *(const float4*)&As[buf][k][ty * 4];
            *(float4*)&ra[4] = *(const float4*)&As[buf][k][64 + ty * 4];
            *(float4*)&rb[0] = *(const float4*)&Bs[buf][k][tx * 4];
            *(float4*)&rb[4] = *(const float4*)&Bs[buf][k][64 + tx * 4];
#pragma unroll
            for (int i = 0; i < 8; i++)
#pragma unroll
                for (int j = 0; j < 8; j++)
                    acc[i][j] += ra[i] * rb[j];
        }
        if (t + 1 < NT) {
            buf ^= 1;
            As[buf][ak+0][ar]=a0.x; As[buf][ak+1][ar]=a0.y; As[buf][ak+2][ar]=a0.z; As[buf][ak+3][ar]=a0.w;
            As[buf][ak+4][ar]=a1.x; As[buf][ak+5][ar]=a1.y; As[buf][ak+6][ar]=a1.z; As[buf][ak+7][ar]=a1.w;
            *(float4*)&Bs[buf][bkr][bc]   = b0;
            *(float4*)&Bs[buf][bkr][bc+4] = b1;
            __syncthreads();
        }
    }

#pragma unroll
    for (int i = 0; i < 8; i++) {
        int r = brow + ((i < 4) ? (ty * 4 + i) : (64 + ty * 4 + i - 4));
        if (r >= M) continue;
#pragma unroll
        for (int jh = 0; jh < 2; jh++) {
            int c = bcol + jh * 64 + tx * 4;
            float4 v;
            v.x = acc[i][jh*4+0]; v.y = acc[i][jh*4+1];
            v.z = acc[i][jh*4+2]; v.w = acc[i][jh*4+3];
            if (bias) { v.x += bias[c]; v.y += bias[c+1]; v.z += bias[c+2]; v.w += bias[c+3]; }
            if (relu) { v.x = fmaxf(v.x,0.f); v.y = fmaxf(v.y,0.f); v.z = fmaxf(v.z,0.f); v.w = fmaxf(v.w,0.f); }
            *(float4*)(C + (long)r * N + c) = v;
        }
    }
}

// ============================================================
// feats transpose: (B, C, HW) -> (B, HW, C)
// ============================================================
__global__ void feats_transpose(const float* __restrict__ feat, float* __restrict__ out)
{
    __shared__ float tile[32][33];
    int b  = blockIdx.z;
    int c0 = blockIdx.x * 32;
    int s0 = blockIdx.y * 32;
    int tx = threadIdx.x, ty = threadIdx.y;
#pragma unroll
    for (int i = 0; i < 32; i += 8)
        tile[ty + i][tx] = feat[((long)b * C_ + c0 + ty + i) * HW + s0 + tx];
    __syncthreads();
#pragma unroll
    for (int i = 0; i < 32; i += 8)
        out[((long)b * HW + s0 + ty + i) * C_ + c0 + tx] = tile[tx][ty + i];
}

__global__ void bcast_queries(const float* __restrict__ qe, float* __restrict__ q)
{
    int i = blockIdx.x * blockDim.x + threadIdx.x;
    if (i < B_ * N_ * C_) q[i] = qe[i % (N_ * C_)];
}

// ============================================================
// attention mask from cur
// ============================================================
__global__ void mask_kernel(const float* __restrict__ cur, unsigned char* __restrict__ am)
{
    int row = blockIdx.x;
    int t = threadIdx.x;
    int y = t >> 5, x = t & 31;
    const float* p = cur + (long)row * HWM;
    int r0 = 4 * y + 1, c0 = 4 * x + 1;
    float v00 = p[r0 * WM + c0],       v01 = p[r0 * WM + c0 + 1];
    float v10 = p[(r0 + 1) * WM + c0], v11 = p[(r0 + 1) * WM + c0 + 1];
    float s = 1.f / (1.f + expf(-v00)) + 1.f / (1.f + expf(-v01))
            + 1.f / (1.f + expf(-v10)) + 1.f / (1.f + expf(-v11));
    int m = (0.25f * s) > 0.5f;

    __shared__ int cnt[32];
    unsigned bal = __ballot_sync(0xffffffffu, m);
    if ((t & 31) == 0) cnt[t >> 5] = __popc(bal);
    __syncthreads();
    if (t < 32) {
        int v = cnt[t];
#pragma unroll
        for (int o = 16; o > 0; o >>= 1) v += __shfl_down_sync(0xffffffffu, v, o);
        if (t == 0) cnt[0] = v;
    }
    __syncthreads();
    am[(long)row * HW + t] = (cnt[0] == 0) ? (unsigned char)1 : (unsigned char)m;
}

// ============================================================
// attention v2 (dynamic smem): block per (h, b); flash-style.
// ============================================================
struct AttnSmem {
    float Ks[128][36];
    float Vs[128][36];
    float qsm[N_][32];
    float psm[8][4][128];
};

extern __shared__ char attn_smem_raw[];

__global__ void __launch_bounds__(256)
attn2(const float* __restrict__ Q, const float* __restrict__ K,
      const float* __restrict__ V, const unsigned char* __restrict__ am,
      float* __restrict__ O)
{
    AttnSmem& sm = *reinterpret_cast<AttnSmem*>(attn_smem_raw);
    int h = blockIdx.x, b = blockIdx.y;

    int tid = threadIdx.x, w = tid >> 5, lane = tid & 31;

    for (int n = w; n < N_; n += 8)
        sm.qsm[n][lane] = Q[((long)(b * N_ + n)) * C_ + h * HD + lane];

    float m[4][4], su[4][4], oa[4][4];
#pragma unroll
    for (int t = 0; t < 4; t++)
#pragma unroll
        for (int qq = 0; qq < 4; qq++) { m[t][qq] = -1e30f; su[t][qq] = 0.f; oa[t][qq] = 0.f; }

    const unsigned char* amb = am + (long)b * N_ * HW;
    const float scale = 0.17677669529663687f;

    for (int c0 = 0; c0 < HW; c0 += 128) {
        __syncthreads();
#pragma unroll
        for (int it = 0; it < 4; it++) {
            int i = tid + it * 256;
            int r = i >> 3, d4 = (i & 7) * 4;
            float4 kv = *(const float4*)(K + ((long)(b * HW + c0 + r)) * C_ + h * HD + d4);
            *(float4*)&sm.Ks[r][d4] = kv;
            float4 vv = *(const float4*)(V + ((long)(b * HW + c0 + r)) * C_ + h * HD + d4);
            *(float4*)&sm.Vs[r][d4] = vv;
        }
        __syncthreads();

#pragma unroll
        for (int t = 0; t < 4; t++) {
            int g = w + 8 * t;
            if (g >= 25) break;

            float dacc[4][4];
#pragma unroll
            for (int qq = 0; qq < 4; qq++)
#pragma unroll
                for (int i = 0; i < 4; i++) dacc[qq][i] = 0.f;

#pragma unroll
            for (int dd4 = 0; dd4 < 8; dd4++) {
                float4 k4[4];
#pragma unroll
                for (int i = 0; i < 4; i++)
                    k4[i] = *(const float4*)&sm.Ks[i * 32 + lane][dd4 * 4];
#pragma unroll
                for (int qq = 0; qq < 4; qq++) {
                    float4 q4 = *(const float4*)&sm.qsm[g * 4 + qq][dd4 * 4];
#pragma unroll
                    for (int i = 0; i < 4; i++)
                        dacc[qq][i] += q4.x*k4[i].x + q4.y*k4[i].y + q4.z*k4[i].z + q4.w*k4[i].w;
                }
            }

            __syncwarp();
#pragma unroll
            for (int qq = 0; qq < 4; qq++) {
                int q = g * 4 + qq;
                const unsigned char* amp = amb + (long)q * HW + c0;
                float sc[4];
#pragma unroll
                for (int i = 0; i < 4; i++) {
                    int s = i * 32 + lane;
                    sc[i] = amp[s] ? dacc[qq][i] * scale : -1e30f;
                }
                float cmax = fmaxf(fmaxf(sc[0], sc[1]), fmaxf(sc[2], sc[3]));
#pragma unroll
                for (int o = 16; o > 0; o >>= 1)
                    cmax = fmaxf(cmax, __shfl_xor_sync(0xffffffffu, cmax, o));
                float nm = fmaxf(m[t][qq], cmax);
                float p[4], ls = 0.f;
#pragma unroll
                for (int i = 0; i < 4; i++) {
                    p[i] = (sc[i] < -1e29f) ? 0.f : __expf(sc[i] - nm);
                    ls += p[i];
                }
#pragma unroll
                for (int o = 16; o > 0; o >>= 1)
                    ls += __shfl_xor_sync(0xffffffffu, ls, o);
                float alpha = __expf(m[t][qq] - nm);
                su[t][qq] = su[t][qq] * alpha + ls;
                oa[t][qq] *= alpha;
                m[t][qq] = nm;
#pragma unroll
                for (int i = 0; i < 4; i++)
                    sm.psm[w][qq][i * 32 + lane] = p[i];
            }
            __syncwarp();

            float po[4] = {0.f, 0.f, 0.f, 0.f};
#pragma unroll
            for (int s4 = 0; s4 < 32; s4++) {
                float v0 = sm.Vs[s4 * 4 + 0][lane];
                float v1 = sm.Vs[s4 * 4 + 1][lane];
                float v2 = sm.Vs[s4 * 4 + 2][lane];
                float v3 = sm.Vs[s4 * 4 + 3][lane];
#pragma unroll
                for (int qq = 0; qq < 4; qq++) {
                    float4 p4 = *(const float4*)&sm.psm[w][qq][s4 * 4];
                    po[qq] += p4.x * v0 + p4.y * v1 + p4.z * v2 + p4.w * v3;
                }
            }
#pragma unroll
            for (int qq = 0; qq < 4; qq++) oa[t][qq] += po[qq];
            __syncwarp();
        }
    }

#pragma unroll
    for (int t = 0; t < 4; t++) {
        int g = w + 8 * t;
        if (g >= 25) break;
#pragma unroll
        for (int qq = 0; qq < 4; qq++)
            O[((long)(b * N_ + g * 4 + qq)) * C_ + h * HD + lane] = oa[t][qq] / su[t][qq];
    }
}

// ============================================================
// LayerNorm over C=256, optional residual
// ============================================================
__global__ void ln_kernel(const float* __restrict__ X, const float* __restrict__ R,
                          const float* __restrict__ g, const float* __restrict__ be,
                          float* __restrict__ Y)
{
    int row = blockIdx.x;
    int t = threadIdx.x;
    float x = X[(long)row * C_ + t];
    if (R) x += R[(long)row * C_ + t];

    __shared__ float red[8];
    float s = x;
#pragma unroll
    for (int o = 16; o > 0; o >>= 1) s += __shfl_xor_sync(0xffffffffu, s, o);
    if ((t & 31) == 0) red[t >> 5] = s;
    __syncthreads();
    if (t < 8) {
        float v = red[t];
#pragma unroll
        for (int o = 4; o > 0; o >>= 1) v += __shfl_xor_sync(0xffu, v, o);
        if (t == 0) red[0] = v;
    }
    __syncthreads();
    float mean = red[0] * (1.f / C_);
    float dv = x - mean;
    float s2 = dv * dv;
    __syncthreads();
#pragma unroll
    for (int o = 16; o > 0; o >>= 1) s2 += __shfl_xor_sync(0xffffffffu, s2, o);
    if ((t & 31) == 0) red[t >> 5] = s2;
    __syncthreads();
    if (t < 8) {
        float v = red[t];
#pragma unroll
        for (int o = 4; o > 0; o >>= 1) v += __shfl_xor_sync(0xffu, v, o);
        if (t == 0) red[0] = v;
    }
    __syncthreads();
    float var = red[0] * (1.f / C_);
    Y[(long)row * C_ + t] = dv * rsqrtf(var + EPSF) * g[t] + be[t];
}

// ============================================================
// host orchestration
// ============================================================
extern "C" void kernel_launch(void* const* d_in, const int* in_sizes, int n_in,
                              void* d_out, int out_size)
{
    (void)in_sizes; (void)n_in; (void)out_size;
    const float* features      = (const float*)d_in[0];
    const float* mask_features = (const float*)d_in[1];
    const float* query_embed   = (const float*)d_in[2];
    const float* Wq  = (const float*)d_in[3];
    const float* bq  = (const float*)d_in[4];
    const float* Wk  = (const float*)d_in[5];
    const float* bk  = (const float*)d_in[6];
    const float* Wv  = (const float*)d_in[7];
    const float* bv  = (const float*)d_in[8];
    const float* Wo  = (const float*)d_in[9];
    const float* bo  = (const float*)d_in[10];
    const float* g1  = (const float*)d_in[11];
    const float* be1 = (const float*)d_in[12];
    const float* W1  = (const float*)d_in[13];
    const float* b1  = (const float*)d_in[14];
    const float* W2  = (const float*)d_in[15];
    const float* b2  = (const float*)d_in[16];
    const float* g2  = (const float*)d_in[17];
    const float* be2 = (const float*)d_in[18];
    const float* gN  = (const float*)d_in[19];
    const float* beN = (const float*)d_in[20];
    const float* Wm1 = (const float*)d_in[21];
    const float* bm1 = (const float*)d_in[22];
    const float* Wm2 = (const float*)d_in[23];
    const float* bm2 = (const float*)d_in[24];
    float* out = (float*)d_out;

    float* S; cudaGetSymbolAddress((void**)&S, g_scratch);
    unsigned char* AM; cudaGetSymbolAddress((void**)&AM, g_am);

    // idempotent, called every time (no static guards per harness contract)
    cudaFuncSetAttribute(attn2, cudaFuncAttributeMaxDynamicSharedMemorySize,
                         (int)sizeof(AttnSmem));

    float* Qcur = S + OFF_Q;
    float* E1   = S + OFF_E1;
    float* E    = S + OFF_E;
    float* QB   = S + OFF_QB;
    float* OB   = S + OFF_OB;
    float* TMP  = S + OFF_TMP;
    float* FFH  = S + OFF_FFH;
    float* FE   = S + OFF_FE;
    float* KB   = S + OFF_KB;
    float* VB   = S + OFF_VB;

    const int MQ = B_ * N_;   // 1600

    feats_transpose<<<dim3(C_ / 32, HW / 32, B_), dim3(32, 8)>>>(features, FE);
    bcast_queries<<<(B_ * N_ * C_ + 255) / 256, 256>>>(query_embed, Qcur);

    for (int l = 0; l < L_; l++) {
        gemm64<<<dim3(C_ / 64, 25, 1), 256>>>(Qcur, Wm1, bm1, E1, MQ, C_, C_, 1, 0, 0, 0);
        gemm64<<<dim3(C_ / 64, 25, 1), 256>>>(E1, Wm2, bm2, E, MQ, C_, C_, 0, 0, 0, 0);
        float* curp = out + OUT_INTER + (long)l * B_ * N_ * HWM;
        gemm128<<<dim3(HWM / 128, 1, B_), 256>>>(E, mask_features, nullptr, curp,
                                                 N_, HWM, C_, 0,
                                                 (long)N_ * C_, (long)C_ * HWM, (long)N_ * HWM);
        mask_kernel<<<MQ, 1024>>>(curp, AM);

        gemm64<<<dim3(C_ / 64, 25, 1), 256>>>(Qcur, Wq + (long)l * C_ * C_, bq + l * C_,
                                              QB, MQ, C_, C_, 0, 0, 0, 0);
        gemm128<<<dim3(C_ / 128, HW * B_ / 128, 1), 256>>>(FE, Wk + (long)l * C_ * C_, bk + l * C_,
                                                           KB, B_ * HW, C_, C_, 0, 0, 0, 0);
        gemm128<<<dim3(C_ / 128, HW * B_ / 128, 1), 256>>>(FE, Wv + (long)l * C_ * C_, bv + l * C_,
                                                           VB, B_ * HW, C_, C_, 0, 0, 0, 0);

        attn2<<<dim3(NH_, B_), 256, sizeof(AttnSmem)>>>(QB, KB, VB, AM, OB);

        gemm64<<<dim3(C_ / 64, 25, 1), 256>>>(OB, Wo + (long)l * C_ * C_, bo + l * C_,
                                              TMP, MQ, C_, C_, 0, 0, 0, 0);
        ln_kernel<<<MQ, C_>>>(Qcur, TMP, g1 + l * C_, be1 + l * C_, Qcur);

        gemm64<<<dim3(F_ / 64, 25, 1), 256>>>(Qcur, W1 + (long)l * C_ * F_, b1 + l * F_,
                                              FFH, MQ, F_, C_, 1, 0, 0, 0);
        gemm64<<<dim3(C_ / 64, 25, 1), 256>>>(FFH, W2 + (long)l * F_ * C_, b2 + l * C_,
                                              TMP, MQ, C_, F_, 0, 0, 0, 0);
        ln_kernel<<<MQ, C_>>>(Qcur, TMP, g2 + l * C_, be2 + l * C_, Qcur);
    }

    ln_kernel<<<MQ, C_>>>(Qcur, nullptr, gN, beN, out + OUT_Q);

    gemm64<<<dim3(C_ / 64, 25, 1), 256>>>(out + OUT_Q, Wm1, bm1, E1, MQ, C_, C_, 1, 0, 0, 0);
    gemm64<<<dim3(C_ / 64, 25, 1), 256>>>(E1, Wm2, bm2, E, MQ, C_, C_, 0, 0, 0, 0);
    gemm128<<<dim3(HWM / 128, 1, B_), 256>>>(E, mask_features, nullptr, out + OUT_PRED,
                                             N_, HWM, C_, 0,
                                             (long)N_ * C_, (long)C_ * HWM, (long)N_ * HWM);
}